// round 1
// baseline (speedup 1.0000x reference)
#include <cuda_runtime.h>
#include <math_constants.h>

// ---------------- problem constants ----------------
#define BB 2
#define NV 6
#define DIMC 128
#define HH 48
#define WW 48
#define QCNT 2304   // 48*48
#define KCNT 576    // 24*24
#define HEADS 4
#define DH 32
#define BH (BB*HEADS)          // 8
#define SCALEF 0.17677669529663689f  // 32^-0.5

typedef unsigned long long u64;

// ---------------- f32x2 packed helpers ----------------
__device__ __forceinline__ u64 f2_fma(u64 a, u64 b, u64 c) {
    u64 d; asm("fma.rn.f32x2 %0,%1,%2,%3;" : "=l"(d) : "l"(a), "l"(b), "l"(c)); return d;
}
__device__ __forceinline__ u64 f2_mul(u64 a, u64 b) {
    u64 d; asm("mul.rn.f32x2 %0,%1,%2;" : "=l"(d) : "l"(a), "l"(b)); return d;
}
__device__ __forceinline__ u64 f2_add(u64 a, u64 b) {
    u64 d; asm("add.rn.f32x2 %0,%1,%2;" : "=l"(d) : "l"(a), "l"(b)); return d;
}
__device__ __forceinline__ u64 f2_pack(float lo, float hi) {
    u64 d; asm("mov.b64 %0,{%1,%2};" : "=l"(d) : "r"(__float_as_uint(lo)), "r"(__float_as_uint(hi))); return d;
}
__device__ __forceinline__ void f2_unpack(float& lo, float& hi, u64 v) {
    unsigned a, b; asm("mov.b64 {%0,%1},%2;" : "=r"(a), "=r"(b) : "l"(v));
    lo = __uint_as_float(a); hi = __uint_as_float(b);
}

// ---------------- scratch (device globals; no allocation allowed) ----------------
__device__ float g_qp[BH * NV * QCNT * DH];     // 3,538,944
__device__ float g_kp[BH * NV * KCNT * DH];     //   884,736
__device__ float g_vp[BH * NV * KCNT * DH];     //   884,736
__device__ float g_Opart[BH * NV * QCNT * DH];  // 3,538,944
__device__ float g_ml[BH * NV * QCNT * 2];      //   221,184
__device__ float g_obuf[BB * QCNT * DIMC];      //   589,824

// ==================================================================
// Kernel 1: LN + projection.  X layout (B,N,128,S) with S spatial.
// Tile: 64 spatial rows, all 128 channels. 256 threads.
// Output scatter: out[((b*4+head)*6+n)*S + row][32] head-split.
// ==================================================================
#define PJP 132
__global__ __launch_bounds__(256) void proj_kernel(
    const float* __restrict__ X,
    const float* __restrict__ lng, const float* __restrict__ lnb,
    const float* __restrict__ Wt, const float* __restrict__ biasv,
    float* __restrict__ outp, int S)
{
    __shared__ float As[64 * PJP];
    __shared__ float s_mean[64], s_rstd[64];
    int tiles = S >> 6;
    int blk = blockIdx.x;
    int t = blk % tiles;
    int bn = blk / tiles;            // b*6+n
    int b = bn / NV, n = bn % NV;
    int s0 = t * 64;
    const float* Xb = X + (size_t)bn * DIMC * S;
    int tid = threadIdx.x;

    // coalesced load (consecutive tid -> consecutive spatial)
    for (int idx = tid; idx < 64 * 128; idx += 256) {
        int c = idx >> 6, r = idx & 63;
        As[r * PJP + c] = Xb[(size_t)c * S + s0 + r];
    }
    __syncthreads();
    if (tid < 64) {
        float s = 0.f, s2 = 0.f;
        const float* row = &As[tid * PJP];
        #pragma unroll 8
        for (int c = 0; c < 128; c++) { float x = row[c]; s += x; s2 += x * x; }
        float mn = s * (1.f / 128.f);
        float vv = s2 * (1.f / 128.f) - mn * mn;
        s_mean[tid] = mn; s_rstd[tid] = rsqrtf(vv + 1e-5f);
    }
    __syncthreads();
    for (int idx = tid; idx < 64 * 128; idx += 256) {
        int r = idx >> 7, c = idx & 127;
        As[r * PJP + c] = (As[r * PJP + c] - s_mean[r]) * s_rstd[r] * lng[c] + lnb[c];
    }
    __syncthreads();

    // GEMM 64x128 * 128x128, per-thread 4 rows x 8 cols
    int rg = tid >> 4;        // 0..15
    int cg = tid & 15;        // 0..15
    int c0 = cg * 8;
    float acc[4][8];
    #pragma unroll
    for (int i = 0; i < 4; i++)
        #pragma unroll
        for (int j = 0; j < 8; j++) acc[i][j] = 0.f;

    #pragma unroll 4
    for (int k = 0; k < 128; k++) {
        float4 wa = *(const float4*)(Wt + k * 128 + c0);
        float4 wb = *(const float4*)(Wt + k * 128 + c0 + 4);
        float w[8] = {wa.x, wa.y, wa.z, wa.w, wb.x, wb.y, wb.z, wb.w};
        float a0 = As[(4 * rg + 0) * PJP + k];
        float a1 = As[(4 * rg + 1) * PJP + k];
        float a2 = As[(4 * rg + 2) * PJP + k];
        float a3 = As[(4 * rg + 3) * PJP + k];
        #pragma unroll
        for (int j = 0; j < 8; j++) {
            acc[0][j] += a0 * w[j];
            acc[1][j] += a1 * w[j];
            acc[2][j] += a2 * w[j];
            acc[3][j] += a3 * w[j];
        }
    }
    float bb[8];
    #pragma unroll
    for (int j = 0; j < 8; j++) bb[j] = biasv[c0 + j];
    int head = c0 >> 5, dh0 = c0 & 31;
    #pragma unroll
    for (int i = 0; i < 4; i++) {
        int qrow = s0 + 4 * rg + i;
        float* dst = outp + ((((size_t)(b * HEADS + head) * NV + n) * S + qrow) * DH + dh0);
        float4 v0 = make_float4(acc[i][0] + bb[0], acc[i][1] + bb[1], acc[i][2] + bb[2], acc[i][3] + bb[3]);
        float4 v1 = make_float4(acc[i][4] + bb[4], acc[i][5] + bb[5], acc[i][6] + bb[6], acc[i][7] + bb[7]);
        *(float4*)(dst) = v0;
        *(float4*)(dst + 4) = v1;
    }
}

// ==================================================================
// Kernel 2: per-view flash attention partials.
// grid (36, 6, 8), 64 threads; thread = one query.
// ==================================================================
__global__ __launch_bounds__(64) void attn_kernel(
    const float* __restrict__ qp, const float* __restrict__ kp,
    const float* __restrict__ vp, float* __restrict__ Opart,
    float* __restrict__ ml)
{
    __shared__ float4 Ksm[512];
    __shared__ float4 Vsm[512];
    int qt = blockIdx.x, n = blockIdx.y, bh = blockIdx.z;
    int tid = threadIdx.x;
    size_t view = (size_t)bh * NV + n;

    const float* qrow = qp + (view * QCNT + qt * 64 + tid) * DH;
    u64 qu[16];
    #pragma unroll
    for (int e = 0; e < 16; e++)
        qu[e] = f2_pack(qrow[2 * e] * SCALEF, qrow[2 * e + 1] * SCALEF);

    u64 Ov[16];
    #pragma unroll
    for (int e = 0; e < 16; e++) Ov[e] = 0ull;
    float m = -CUDART_INF_F, l = 0.f;

    const float4* Kb = (const float4*)(kp + view * KCNT * DH);
    const float4* Vb = (const float4*)(vp + view * KCNT * DH);

    for (int c0 = 0; c0 < KCNT; c0 += 64) {
        __syncthreads();
        #pragma unroll
        for (int i = 0; i < 8; i++) {
            int f = i * 64 + tid;
            Ksm[f] = Kb[c0 * 8 + f];
            Vsm[f] = Vb[c0 * 8 + f];
        }
        __syncthreads();
        for (int g2 = 0; g2 < 8; g2++) {
            float sc[8];
            #pragma unroll
            for (int j = 0; j < 8; j++) {
                const double2* Kr = (const double2*)&Ksm[(g2 * 8 + j) * 8];
                u64 a0 = 0, a1 = 0, a2 = 0, a3 = 0;
                #pragma unroll
                for (int i = 0; i < 4; i++) {
                    double2 d0 = Kr[2 * i];
                    double2 d1 = Kr[2 * i + 1];
                    a0 = f2_fma(qu[4 * i + 0], __double_as_longlong(d0.x), a0);
                    a1 = f2_fma(qu[4 * i + 1], __double_as_longlong(d0.y), a1);
                    a2 = f2_fma(qu[4 * i + 2], __double_as_longlong(d1.x), a2);
                    a3 = f2_fma(qu[4 * i + 3], __double_as_longlong(d1.y), a3);
                }
                u64 s01 = f2_add(f2_add(a0, a1), f2_add(a2, a3));
                float lo, hi; f2_unpack(lo, hi, s01);
                sc[j] = lo + hi;
            }
            float gm = sc[0];
            #pragma unroll
            for (int j = 1; j < 8; j++) gm = fmaxf(gm, sc[j]);
            if (gm > m) {
                float sf = __expf(m - gm);   // m=-inf -> 0
                l *= sf;
                u64 s2 = f2_pack(sf, sf);
                #pragma unroll
                for (int e = 0; e < 16; e++) Ov[e] = f2_mul(Ov[e], s2);
                m = gm;
            }
            #pragma unroll
            for (int j = 0; j < 8; j++) {
                float p = __expf(sc[j] - m);
                l += p;
                u64 pp = f2_pack(p, p);
                const double2* Vr = (const double2*)&Vsm[(g2 * 8 + j) * 8];
                #pragma unroll
                for (int i = 0; i < 8; i++) {
                    double2 vv = Vr[i];
                    Ov[2 * i]     = f2_fma(pp, __double_as_longlong(vv.x), Ov[2 * i]);
                    Ov[2 * i + 1] = f2_fma(pp, __double_as_longlong(vv.y), Ov[2 * i + 1]);
                }
            }
        }
    }
    size_t orow = view * QCNT + qt * 64 + tid;
    u64* dst = (u64*)(Opart + orow * DH);
    #pragma unroll
    for (int e = 0; e < 16; e++) dst[e] = Ov[e];
    ml[orow * 2] = m;
    ml[orow * 2 + 1] = l;
}

// ==================================================================
// Kernel 3: merge the 6 per-view partials -> obuf[(b*Q+q)*128 + head*32+dh]
// ==================================================================
__global__ __launch_bounds__(256) void combine_kernel(
    const float* __restrict__ Opart, const float* __restrict__ ml,
    float* __restrict__ obuf)
{
    int idx = blockIdx.x * 256 + threadIdx.x;   // exactly 589824 threads
    int hd = idx & 127;
    int rq = idx >> 7;                           // b*2304+q
    int b = rq / QCNT, q = rq - b * QCNT;
    int head = hd >> 5, dh = hd & 31;
    size_t bh = (size_t)b * HEADS + head;
    float mv[6], lv[6], M = -CUDART_INF_F;
    #pragma unroll
    for (int n = 0; n < NV; n++) {
        size_t row = (bh * NV + n) * QCNT + q;
        mv[n] = ml[row * 2];
        lv[n] = ml[row * 2 + 1];
        M = fmaxf(M, mv[n]);
    }
    float L = 0.f, o = 0.f;
    #pragma unroll
    for (int n = 0; n < NV; n++) {
        float w = __expf(mv[n] - M);
        L += w * lv[n];
        o += w * Opart[((bh * NV + n) * QCNT + q) * DH + dh];
    }
    obuf[(size_t)rq * DIMC + hd] = o / L;
}

// ==================================================================
// Kernel 4: out-proj + skip + preLN + MLP(gelu exact) + postLN + transpose out
// Tile 32 rows, 256 threads, per-thread 2 rows x 8 cols.
// ==================================================================
#define CTP 132
__global__ __launch_bounds__(256) void tail_kernel(
    const float* __restrict__ obuf, const float* __restrict__ skip,
    const float* __restrict__ Wpm, const float* __restrict__ bpv,
    const float* __restrict__ preg, const float* __restrict__ preb,
    const float* __restrict__ W1m, const float* __restrict__ b1v,
    const float* __restrict__ W2m, const float* __restrict__ b2v,
    const float* __restrict__ postg, const float* __restrict__ postb,
    float* __restrict__ outp)
{
    __shared__ float As[32 * CTP];
    __shared__ float Bs[32 * CTP];
    __shared__ float sm[32], sr[32];
    int tid = threadIdx.x;
    int gr0 = blockIdx.x * 32;          // rows are b*2304+q
    int b = gr0 / QCNT, q0 = gr0 - b * QCNT;

    for (int idx = tid; idx < 4096; idx += 256) {
        int r = idx >> 7, c = idx & 127;
        As[r * CTP + c] = obuf[(size_t)(gr0 + r) * DIMC + c];
    }
    __syncthreads();

    int rg = tid >> 4, cg = tid & 15, c0 = cg * 8;
    // ---- GEMM1: z = A @ Wp ----
    {
        float acc[2][8];
        #pragma unroll
        for (int i = 0; i < 2; i++)
            #pragma unroll
            for (int j = 0; j < 8; j++) acc[i][j] = 0.f;
        #pragma unroll 4
        for (int k = 0; k < 128; k++) {
            float4 wa = *(const float4*)(Wpm + k * 128 + c0);
            float4 wb = *(const float4*)(Wpm + k * 128 + c0 + 4);
            float w[8] = {wa.x, wa.y, wa.z, wa.w, wb.x, wb.y, wb.z, wb.w};
            float a0 = As[(2 * rg) * CTP + k];
            float a1 = As[(2 * rg + 1) * CTP + k];
            #pragma unroll
            for (int j = 0; j < 8; j++) { acc[0][j] += a0 * w[j]; acc[1][j] += a1 * w[j]; }
        }
        #pragma unroll
        for (int i = 0; i < 2; i++)
            #pragma unroll
            for (int j = 0; j < 8; j++)
                Bs[(2 * rg + i) * CTP + c0 + j] = acc[i][j] + bpv[c0 + j];
    }
    __syncthreads();
    // ---- + skip (coalesced over spatial) ----
    for (int idx = tid; idx < 4096; idx += 256) {
        int c = idx >> 5, r = idx & 31;
        Bs[r * CTP + c] += skip[((size_t)(b * DIMC + c)) * QCNT + q0 + r];
    }
    __syncthreads();
    // ---- pre-LN ----
    if (tid < 32) {
        float s = 0.f, s2 = 0.f;
        const float* row = &Bs[tid * CTP];
        #pragma unroll 8
        for (int c = 0; c < 128; c++) { float x = row[c]; s += x; s2 += x * x; }
        float mn = s * (1.f / 128.f);
        float vv = s2 * (1.f / 128.f) - mn * mn;
        sm[tid] = mn; sr[tid] = rsqrtf(vv + 1e-5f);
    }
    __syncthreads();
    for (int idx = tid; idx < 4096; idx += 256) {
        int r = idx >> 7, c = idx & 127;
        Bs[r * CTP + c] = (Bs[r * CTP + c] - sm[r]) * sr[r] * preg[c] + preb[c];
    }
    __syncthreads();
    // ---- MLP: two column-halves of W1, accumulate GEMM2 into regs ----
    float acc2[2][8];
    #pragma unroll
    for (int i = 0; i < 2; i++)
        #pragma unroll
        for (int j = 0; j < 8; j++) acc2[i][j] = 0.f;
    for (int half = 0; half < 2; half++) {
        float h[2][8];
        #pragma unroll
        for (int i = 0; i < 2; i++)
            #pragma unroll
            for (int j = 0; j < 8; j++) h[i][j] = 0.f;
        #pragma unroll 4
        for (int k = 0; k < 128; k++) {
            float4 wa = *(const float4*)(W1m + k * 256 + half * 128 + c0);
            float4 wb = *(const float4*)(W1m + k * 256 + half * 128 + c0 + 4);
            float w[8] = {wa.x, wa.y, wa.z, wa.w, wb.x, wb.y, wb.z, wb.w};
            float a0 = Bs[(2 * rg) * CTP + k];
            float a1 = Bs[(2 * rg + 1) * CTP + k];
            #pragma unroll
            for (int j = 0; j < 8; j++) { h[0][j] += a0 * w[j]; h[1][j] += a1 * w[j]; }
        }
        #pragma unroll
        for (int i = 0; i < 2; i++)
            #pragma unroll
            for (int j = 0; j < 8; j++) {
                float x = h[i][j] + b1v[half * 128 + c0 + j];
                As[(2 * rg + i) * CTP + c0 + j] = 0.5f * x * (1.f + erff(x * 0.70710678118654752f));
            }
        __syncthreads();
        #pragma unroll 4
        for (int k = 0; k < 128; k++) {
            float4 wa = *(const float4*)(W2m + (half * 128 + k) * 128 + c0);
            float4 wb = *(const float4*)(W2m + (half * 128 + k) * 128 + c0 + 4);
            float w[8] = {wa.x, wa.y, wa.z, wa.w, wb.x, wb.y, wb.z, wb.w};
            float a0 = As[(2 * rg) * CTP + k];
            float a1 = As[(2 * rg + 1) * CTP + k];
            #pragma unroll
            for (int j = 0; j < 8; j++) { acc2[0][j] += a0 * w[j]; acc2[1][j] += a1 * w[j]; }
        }
        __syncthreads();
    }
    #pragma unroll
    for (int i = 0; i < 2; i++)
        #pragma unroll
        for (int j = 0; j < 8; j++)
            Bs[(2 * rg + i) * CTP + c0 + j] += acc2[i][j] + b2v[c0 + j];
    __syncthreads();
    // ---- post-LN ----
    if (tid < 32) {
        float s = 0.f, s2 = 0.f;
        const float* row = &Bs[tid * CTP];
        #pragma unroll 8
        for (int c = 0; c < 128; c++) { float x = row[c]; s += x; s2 += x * x; }
        float mn = s * (1.f / 128.f);
        float vv = s2 * (1.f / 128.f) - mn * mn;
        sm[tid] = mn; sr[tid] = rsqrtf(vv + 1e-5f);
    }
    __syncthreads();
    // ---- write transposed output (B, d, H, W) ----
    for (int idx = tid; idx < 4096; idx += 256) {
        int c = idx >> 5, r = idx & 31;
        float z = (Bs[r * CTP + c] - sm[r]) * sr[r] * postg[c] + postb[c];
        outp[((size_t)(b * DIMC + c)) * QCNT + q0 + r] = z;
    }
}

// ==================================================================
extern "C" void kernel_launch(void* const* d_in, const int* in_sizes, int n_in,
                              void* d_out, int out_size)
{
    const float* q     = (const float*)d_in[0];
    const float* k     = (const float*)d_in[1];
    const float* v     = (const float*)d_in[2];
    const float* skip  = (const float*)d_in[3];
    const float* lnq_g = (const float*)d_in[4];
    const float* lnq_b = (const float*)d_in[5];
    const float* Wq    = (const float*)d_in[6];
    const float* bq    = (const float*)d_in[7];
    const float* lnk_g = (const float*)d_in[8];
    const float* lnk_b = (const float*)d_in[9];
    const float* Wk    = (const float*)d_in[10];
    const float* bk    = (const float*)d_in[11];
    const float* lnv_g = (const float*)d_in[12];
    const float* lnv_b = (const float*)d_in[13];
    const float* Wv    = (const float*)d_in[14];
    const float* bv    = (const float*)d_in[15];
    const float* Wp    = (const float*)d_in[16];
    const float* bp    = (const float*)d_in[17];
    const float* pre_g = (const float*)d_in[18];
    const float* pre_b = (const float*)d_in[19];
    const float* W1    = (const float*)d_in[20];
    const float* b1    = (const float*)d_in[21];
    const float* W2    = (const float*)d_in[22];
    const float* b2    = (const float*)d_in[23];
    const float* post_g= (const float*)d_in[24];
    const float* post_b= (const float*)d_in[25];
    float* outp = (float*)d_out;

    float *qp, *kpb, *vpb, *Opart, *mlb, *obuf;
    cudaGetSymbolAddress((void**)&qp,   g_qp);
    cudaGetSymbolAddress((void**)&kpb,  g_kp);
    cudaGetSymbolAddress((void**)&vpb,  g_vp);
    cudaGetSymbolAddress((void**)&Opart,g_Opart);
    cudaGetSymbolAddress((void**)&mlb,  g_ml);
    cudaGetSymbolAddress((void**)&obuf, g_obuf);

    proj_kernel<<<BB * NV * (QCNT / 64), 256>>>(q, lnq_g, lnq_b, Wq, bq, qp,  QCNT);
    proj_kernel<<<BB * NV * (KCNT / 64), 256>>>(k, lnk_g, lnk_b, Wk, bk, kpb, KCNT);
    proj_kernel<<<BB * NV * (KCNT / 64), 256>>>(v, lnv_g, lnv_b, Wv, bv, vpb, KCNT);

    dim3 ag(QCNT / 64, NV, BH);
    attn_kernel<<<ag, 64>>>(qp, kpb, vpb, Opart, mlb);

    combine_kernel<<<(BB * QCNT * DIMC) / 256, 256>>>(Opart, mlb, obuf);

    tail_kernel<<<(BB * QCNT) / 32, 256>>>(obuf, skip, Wp, bp, pre_g, pre_b,
                                           W1, b1, W2, b2, post_g, post_b, outp);
}

// round 2
// speedup vs baseline: 1.4880x; 1.4880x over previous
#include <cuda_runtime.h>
#include <math_constants.h>

// ---------------- problem constants ----------------
#define BB 2
#define NV 6
#define DIMC 128
#define QCNT 2304   // 48*48
#define KCNT 576    // 24*24
#define HEADS 4
#define DH 32
#define BH (BB*HEADS)          // 8
#define SCALEF 0.17677669529663689f  // 32^-0.5

typedef unsigned long long u64;

// ---------------- f32x2 packed helpers ----------------
__device__ __forceinline__ u64 f2_fma(u64 a, u64 b, u64 c) {
    u64 d; asm("fma.rn.f32x2 %0,%1,%2,%3;" : "=l"(d) : "l"(a), "l"(b), "l"(c)); return d;
}
__device__ __forceinline__ u64 f2_mul(u64 a, u64 b) {
    u64 d; asm("mul.rn.f32x2 %0,%1,%2;" : "=l"(d) : "l"(a), "l"(b)); return d;
}
__device__ __forceinline__ u64 f2_add(u64 a, u64 b) {
    u64 d; asm("add.rn.f32x2 %0,%1,%2;" : "=l"(d) : "l"(a), "l"(b)); return d;
}
__device__ __forceinline__ u64 f2_pack(float lo, float hi) {
    u64 d; asm("mov.b64 %0,{%1,%2};" : "=l"(d) : "r"(__float_as_uint(lo)), "r"(__float_as_uint(hi))); return d;
}
__device__ __forceinline__ void f2_unpack(float& lo, float& hi, u64 v) {
    unsigned a, b; asm("mov.b64 {%0,%1},%2;" : "=r"(a), "=r"(b) : "l"(v));
    lo = __uint_as_float(a); hi = __uint_as_float(b);
}

// ---------------- scratch (device globals; no allocation allowed) ----------------
__device__ float g_qp[BH * NV * QCNT * DH];
__device__ float g_kp[BH * NV * KCNT * DH];
__device__ float g_vp[BH * NV * KCNT * DH];
__device__ float g_Opart[BH * NV * QCNT * DH];
__device__ float g_ml[BH * NV * QCNT * 2];

// ==================================================================
// Kernel 1: LN + projection for q,k,v in ONE launch.
// blocks [0,432) -> q,  [432,540) -> k,  [540,648) -> v
// Tile: 64 spatial rows, all 128 channels. 256 threads.
// ==================================================================
#define PJP 132
__global__ __launch_bounds__(256) void proj_all_kernel(
    const float* __restrict__ qi, const float* __restrict__ ki, const float* __restrict__ vi,
    const float* __restrict__ lnqg, const float* __restrict__ lnqb,
    const float* __restrict__ Wq, const float* __restrict__ bq,
    const float* __restrict__ lnkg, const float* __restrict__ lnkb,
    const float* __restrict__ Wk, const float* __restrict__ bk,
    const float* __restrict__ lnvg, const float* __restrict__ lnvb,
    const float* __restrict__ Wv, const float* __restrict__ bv,
    float* __restrict__ qo, float* __restrict__ ko, float* __restrict__ vo)
{
    __shared__ float As[64 * PJP];
    __shared__ float s_mean[64], s_rstd[64];
    int blk = blockIdx.x;
    const float* X; const float* lng; const float* lnb;
    const float* Wt; const float* biasv; float* outp; int S; int local;
    if (blk < 432)      { X = qi; lng = lnqg; lnb = lnqb; Wt = Wq; biasv = bq; outp = qo; S = QCNT; local = blk; }
    else if (blk < 540) { X = ki; lng = lnkg; lnb = lnkb; Wt = Wk; biasv = bk; outp = ko; S = KCNT; local = blk - 432; }
    else                { X = vi; lng = lnvg; lnb = lnvb; Wt = Wv; biasv = bv; outp = vo; S = KCNT; local = blk - 540; }

    int tiles = S >> 6;
    int t = local % tiles;
    int bn = local / tiles;            // b*6+n
    int b = bn / NV, n = bn % NV;
    int s0 = t * 64;
    const float* Xb = X + (size_t)bn * DIMC * S;
    int tid = threadIdx.x;

    for (int idx = tid; idx < 64 * 128; idx += 256) {
        int c = idx >> 6, r = idx & 63;
        As[r * PJP + c] = Xb[(size_t)c * S + s0 + r];
    }
    __syncthreads();
    if (tid < 64) {
        float s = 0.f, s2 = 0.f;
        const float* row = &As[tid * PJP];
        #pragma unroll 8
        for (int c = 0; c < 128; c++) { float x = row[c]; s += x; s2 += x * x; }
        float mn = s * (1.f / 128.f);
        float vv = s2 * (1.f / 128.f) - mn * mn;
        s_mean[tid] = mn; s_rstd[tid] = rsqrtf(vv + 1e-5f);
    }
    __syncthreads();
    for (int idx = tid; idx < 64 * 128; idx += 256) {
        int r = idx >> 7, c = idx & 127;
        As[r * PJP + c] = (As[r * PJP + c] - s_mean[r]) * s_rstd[r] * lng[c] + lnb[c];
    }
    __syncthreads();

    // GEMM 64x128 * 128x128, per-thread 4 rows x 8 cols, packed f32x2
    int rg = tid >> 4;        // 0..15
    int cg = tid & 15;        // 0..15
    int c0 = cg * 8;
    u64 acc[4][4];
    #pragma unroll
    for (int i = 0; i < 4; i++)
        #pragma unroll
        for (int j = 0; j < 4; j++) acc[i][j] = 0ull;

    #pragma unroll 4
    for (int k = 0; k < 128; k++) {
        const double* Wd = (const double*)(Wt + k * 128 + c0);
        u64 w0 = __double_as_longlong(Wd[0]);
        u64 w1 = __double_as_longlong(Wd[1]);
        u64 w2 = __double_as_longlong(Wd[2]);
        u64 w3 = __double_as_longlong(Wd[3]);
        u64 a0 = f2_pack(As[(4 * rg + 0) * PJP + k], As[(4 * rg + 0) * PJP + k]);
        u64 a1 = f2_pack(As[(4 * rg + 1) * PJP + k], As[(4 * rg + 1) * PJP + k]);
        u64 a2 = f2_pack(As[(4 * rg + 2) * PJP + k], As[(4 * rg + 2) * PJP + k]);
        u64 a3 = f2_pack(As[(4 * rg + 3) * PJP + k], As[(4 * rg + 3) * PJP + k]);
        acc[0][0] = f2_fma(a0, w0, acc[0][0]); acc[0][1] = f2_fma(a0, w1, acc[0][1]);
        acc[0][2] = f2_fma(a0, w2, acc[0][2]); acc[0][3] = f2_fma(a0, w3, acc[0][3]);
        acc[1][0] = f2_fma(a1, w0, acc[1][0]); acc[1][1] = f2_fma(a1, w1, acc[1][1]);
        acc[1][2] = f2_fma(a1, w2, acc[1][2]); acc[1][3] = f2_fma(a1, w3, acc[1][3]);
        acc[2][0] = f2_fma(a2, w0, acc[2][0]); acc[2][1] = f2_fma(a2, w1, acc[2][1]);
        acc[2][2] = f2_fma(a2, w2, acc[2][2]); acc[2][3] = f2_fma(a2, w3, acc[2][3]);
        acc[3][0] = f2_fma(a3, w0, acc[3][0]); acc[3][1] = f2_fma(a3, w1, acc[3][1]);
        acc[3][2] = f2_fma(a3, w2, acc[3][2]); acc[3][3] = f2_fma(a3, w3, acc[3][3]);
    }
    const double* Bd = (const double*)(biasv + c0);
    u64 bb0 = __double_as_longlong(Bd[0]);
    u64 bb1 = __double_as_longlong(Bd[1]);
    u64 bb2 = __double_as_longlong(Bd[2]);
    u64 bb3 = __double_as_longlong(Bd[3]);
    int head = c0 >> 5, dh0 = c0 & 31;
    #pragma unroll
    for (int i = 0; i < 4; i++) {
        int qrow = s0 + 4 * rg + i;
        u64* dst = (u64*)(outp + ((((size_t)(b * HEADS + head) * NV + n) * S + qrow) * DH + dh0));
        dst[0] = f2_add(acc[i][0], bb0);
        dst[1] = f2_add(acc[i][1], bb1);
        dst[2] = f2_add(acc[i][2], bb2);
        dst[3] = f2_add(acc[i][3], bb3);
    }
}

// ==================================================================
// Kernel 2: per-view flash attention partials. 2 queries per thread.
// grid (18, 6, 8), 64 threads; thread = queries (qt*128+tid, qt*128+64+tid)
// ==================================================================
__global__ __launch_bounds__(64) void attn_kernel(
    const float* __restrict__ qp, const float* __restrict__ kp,
    const float* __restrict__ vp, float* __restrict__ Opart,
    float* __restrict__ ml)
{
    __shared__ float4 Ksm[512];
    __shared__ float4 Vsm[512];
    int qt = blockIdx.x, n = blockIdx.y, bh = blockIdx.z;
    int tid = threadIdx.x;
    size_t view = (size_t)bh * NV + n;

    u64 qu[2][16];
    #pragma unroll
    for (int s = 0; s < 2; s++) {
        const float* qrow = qp + (view * QCNT + qt * 128 + s * 64 + tid) * DH;
        #pragma unroll
        for (int e = 0; e < 16; e++)
            qu[s][e] = f2_pack(qrow[2 * e] * SCALEF, qrow[2 * e + 1] * SCALEF);
    }
    u64 Ov[2][16];
    #pragma unroll
    for (int s = 0; s < 2; s++)
        #pragma unroll
        for (int e = 0; e < 16; e++) Ov[s][e] = 0ull;
    float m0 = -CUDART_INF_F, m1 = -CUDART_INF_F, l0 = 0.f, l1 = 0.f;

    const float4* Kb = (const float4*)(kp + view * KCNT * DH);
    const float4* Vb = (const float4*)(vp + view * KCNT * DH);

    for (int c0 = 0; c0 < KCNT; c0 += 64) {
        __syncthreads();
        #pragma unroll
        for (int i = 0; i < 8; i++) {
            int f = i * 64 + tid;
            Ksm[f] = Kb[c0 * 8 + f];
            Vsm[f] = Vb[c0 * 8 + f];
        }
        __syncthreads();
        #pragma unroll 1
        for (int g = 0; g < 8; g++) {
            float sc0[8], sc1[8];
            #pragma unroll
            for (int j = 0; j < 8; j++) {
                const double2* Kr = (const double2*)&Ksm[(g * 8 + j) * 8];
                u64 a00 = 0, a01 = 0, a10 = 0, a11 = 0;
                #pragma unroll
                for (int i = 0; i < 4; i++) {
                    double2 d0 = Kr[2 * i];
                    double2 d1 = Kr[2 * i + 1];
                    u64 k0 = __double_as_longlong(d0.x), k1 = __double_as_longlong(d0.y);
                    u64 k2 = __double_as_longlong(d1.x), k3 = __double_as_longlong(d1.y);
                    a00 = f2_fma(qu[0][4 * i + 0], k0, a00);
                    a01 = f2_fma(qu[0][4 * i + 1], k1, a01);
                    a00 = f2_fma(qu[0][4 * i + 2], k2, a00);
                    a01 = f2_fma(qu[0][4 * i + 3], k3, a01);
                    a10 = f2_fma(qu[1][4 * i + 0], k0, a10);
                    a11 = f2_fma(qu[1][4 * i + 1], k1, a11);
                    a10 = f2_fma(qu[1][4 * i + 2], k2, a10);
                    a11 = f2_fma(qu[1][4 * i + 3], k3, a11);
                }
                float lo, hi;
                f2_unpack(lo, hi, f2_add(a00, a01)); sc0[j] = lo + hi;
                f2_unpack(lo, hi, f2_add(a10, a11)); sc1[j] = lo + hi;
            }
            float gm0 = sc0[0], gm1 = sc1[0];
            #pragma unroll
            for (int j = 1; j < 8; j++) { gm0 = fmaxf(gm0, sc0[j]); gm1 = fmaxf(gm1, sc1[j]); }
            if (gm0 > m0) {
                float sf = __expf(m0 - gm0);   // m=-inf -> 0
                l0 *= sf;
                u64 s2 = f2_pack(sf, sf);
                #pragma unroll
                for (int e = 0; e < 16; e++) Ov[0][e] = f2_mul(Ov[0][e], s2);
                m0 = gm0;
            }
            if (gm1 > m1) {
                float sf = __expf(m1 - gm1);
                l1 *= sf;
                u64 s2 = f2_pack(sf, sf);
                #pragma unroll
                for (int e = 0; e < 16; e++) Ov[1][e] = f2_mul(Ov[1][e], s2);
                m1 = gm1;
            }
            #pragma unroll
            for (int j = 0; j < 8; j++) {
                float p0 = __expf(sc0[j] - m0); l0 += p0;
                float p1 = __expf(sc1[j] - m1); l1 += p1;
                u64 pp0 = f2_pack(p0, p0);
                u64 pp1 = f2_pack(p1, p1);
                const double2* Vr = (const double2*)&Vsm[(g * 8 + j) * 8];
                #pragma unroll
                for (int i = 0; i < 4; i++) {
                    double2 v0 = Vr[2 * i];
                    double2 v1 = Vr[2 * i + 1];
                    u64 x0 = __double_as_longlong(v0.x), x1 = __double_as_longlong(v0.y);
                    u64 x2 = __double_as_longlong(v1.x), x3 = __double_as_longlong(v1.y);
                    Ov[0][4 * i + 0] = f2_fma(pp0, x0, Ov[0][4 * i + 0]);
                    Ov[0][4 * i + 1] = f2_fma(pp0, x1, Ov[0][4 * i + 1]);
                    Ov[0][4 * i + 2] = f2_fma(pp0, x2, Ov[0][4 * i + 2]);
                    Ov[0][4 * i + 3] = f2_fma(pp0, x3, Ov[0][4 * i + 3]);
                    Ov[1][4 * i + 0] = f2_fma(pp1, x0, Ov[1][4 * i + 0]);
                    Ov[1][4 * i + 1] = f2_fma(pp1, x1, Ov[1][4 * i + 1]);
                    Ov[1][4 * i + 2] = f2_fma(pp1, x2, Ov[1][4 * i + 2]);
                    Ov[1][4 * i + 3] = f2_fma(pp1, x3, Ov[1][4 * i + 3]);
                }
            }
        }
    }
    #pragma unroll
    for (int s = 0; s < 2; s++) {
        size_t orow = view * QCNT + qt * 128 + s * 64 + tid;
        u64* dst = (u64*)(Opart + orow * DH);
        #pragma unroll
        for (int e = 0; e < 16; e++) dst[e] = Ov[s][e];
        ml[orow * 2]     = s ? m1 : m0;
        ml[orow * 2 + 1] = s ? l1 : l0;
    }
}

// ==================================================================
// Kernel 3: fused combine + out-proj + skip + preLN + MLP + postLN + transpose
// Tile 32 rows, 256 threads.
// ==================================================================
#define CTP 132
__global__ __launch_bounds__(256) void tail_kernel(
    const float* __restrict__ Opart, const float* __restrict__ ml,
    const float* __restrict__ skip,
    const float* __restrict__ Wpm, const float* __restrict__ bpv,
    const float* __restrict__ preg, const float* __restrict__ preb,
    const float* __restrict__ W1m, const float* __restrict__ b1v,
    const float* __restrict__ W2m, const float* __restrict__ b2v,
    const float* __restrict__ postg, const float* __restrict__ postb,
    float* __restrict__ outp)
{
    __shared__ float As[32 * CTP];
    __shared__ float Bs[32 * CTP];
    __shared__ float sm[32], sr[32];
    int tid = threadIdx.x;
    int gr0 = blockIdx.x * 32;          // rows are b*2304+q
    int b = gr0 / QCNT, q0 = gr0 - b * QCNT;

    // ---- fused combine: merge 6 per-view partials into As ----
    for (int idx = tid; idx < 4096; idx += 256) {
        int r = idx >> 7, c = idx & 127;
        int q = q0 + r;
        int head = c >> 5, dh = c & 31;
        size_t bhx = (size_t)b * HEADS + head;
        float mv[6], lv[6], M = -CUDART_INF_F;
        #pragma unroll
        for (int n = 0; n < NV; n++) {
            size_t row = (bhx * NV + n) * QCNT + q;
            mv[n] = ml[row * 2];
            lv[n] = ml[row * 2 + 1];
            M = fmaxf(M, mv[n]);
        }
        float L = 0.f, o = 0.f;
        #pragma unroll
        for (int n = 0; n < NV; n++) {
            float w = __expf(mv[n] - M);
            L += w * lv[n];
            o += w * Opart[((bhx * NV + n) * QCNT + q) * DH + dh];
        }
        As[r * CTP + c] = __fdividef(o, L);
    }
    __syncthreads();

    int rg = tid >> 4, cg = tid & 15, c0 = cg * 8;
    // ---- GEMM1: z = A @ Wp ----
    {
        u64 acc[2][4];
        #pragma unroll
        for (int i = 0; i < 2; i++)
            #pragma unroll
            for (int j = 0; j < 4; j++) acc[i][j] = 0ull;
        #pragma unroll 4
        for (int k = 0; k < 128; k++) {
            const double* Wd = (const double*)(Wpm + k * 128 + c0);
            u64 w0 = __double_as_longlong(Wd[0]);
            u64 w1 = __double_as_longlong(Wd[1]);
            u64 w2 = __double_as_longlong(Wd[2]);
            u64 w3 = __double_as_longlong(Wd[3]);
            float s0 = As[(2 * rg) * CTP + k];
            float s1 = As[(2 * rg + 1) * CTP + k];
            u64 a0 = f2_pack(s0, s0);
            u64 a1 = f2_pack(s1, s1);
            acc[0][0] = f2_fma(a0, w0, acc[0][0]); acc[0][1] = f2_fma(a0, w1, acc[0][1]);
            acc[0][2] = f2_fma(a0, w2, acc[0][2]); acc[0][3] = f2_fma(a0, w3, acc[0][3]);
            acc[1][0] = f2_fma(a1, w0, acc[1][0]); acc[1][1] = f2_fma(a1, w1, acc[1][1]);
            acc[1][2] = f2_fma(a1, w2, acc[1][2]); acc[1][3] = f2_fma(a1, w3, acc[1][3]);
        }
        const double* bd = (const double*)(bpv + c0);
        #pragma unroll
        for (int i = 0; i < 2; i++) {
            u64* dst = (u64*)&Bs[(2 * rg + i) * CTP + c0];
            #pragma unroll
            for (int j = 0; j < 4; j++)
                dst[j] = f2_add(acc[i][j], __double_as_longlong(bd[j]));
        }
    }
    __syncthreads();
    // ---- + skip (coalesced over spatial) ----
    for (int idx = tid; idx < 4096; idx += 256) {
        int c = idx >> 5, r = idx & 31;
        Bs[r * CTP + c] += skip[((size_t)(b * DIMC + c)) * QCNT + q0 + r];
    }
    __syncthreads();
    // ---- pre-LN ----
    if (tid < 32) {
        float s = 0.f, s2 = 0.f;
        const float* row = &Bs[tid * CTP];
        #pragma unroll 8
        for (int c = 0; c < 128; c++) { float x = row[c]; s += x; s2 += x * x; }
        float mn = s * (1.f / 128.f);
        float vv = s2 * (1.f / 128.f) - mn * mn;
        sm[tid] = mn; sr[tid] = rsqrtf(vv + 1e-5f);
    }
    __syncthreads();
    for (int idx = tid; idx < 4096; idx += 256) {
        int r = idx >> 7, c = idx & 127;
        Bs[r * CTP + c] = (Bs[r * CTP + c] - sm[r]) * sr[r] * preg[c] + preb[c];
    }
    __syncthreads();
    // ---- MLP: two column-halves of W1, accumulate GEMM2 into regs ----
    u64 acc2[2][4];
    #pragma unroll
    for (int i = 0; i < 2; i++)
        #pragma unroll
        for (int j = 0; j < 4; j++) acc2[i][j] = 0ull;
    for (int half = 0; half < 2; half++) {
        u64 h[2][4];
        #pragma unroll
        for (int i = 0; i < 2; i++)
            #pragma unroll
            for (int j = 0; j < 4; j++) h[i][j] = 0ull;
        #pragma unroll 4
        for (int k = 0; k < 128; k++) {
            const double* Wd = (const double*)(W1m + k * 256 + half * 128 + c0);
            u64 w0 = __double_as_longlong(Wd[0]);
            u64 w1 = __double_as_longlong(Wd[1]);
            u64 w2 = __double_as_longlong(Wd[2]);
            u64 w3 = __double_as_longlong(Wd[3]);
            float s0 = Bs[(2 * rg) * CTP + k];
            float s1 = Bs[(2 * rg + 1) * CTP + k];
            u64 a0 = f2_pack(s0, s0);
            u64 a1 = f2_pack(s1, s1);
            h[0][0] = f2_fma(a0, w0, h[0][0]); h[0][1] = f2_fma(a0, w1, h[0][1]);
            h[0][2] = f2_fma(a0, w2, h[0][2]); h[0][3] = f2_fma(a0, w3, h[0][3]);
            h[1][0] = f2_fma(a1, w0, h[1][0]); h[1][1] = f2_fma(a1, w1, h[1][1]);
            h[1][2] = f2_fma(a1, w2, h[1][2]); h[1][3] = f2_fma(a1, w3, h[1][3]);
        }
        const double* b1d = (const double*)(b1v + half * 128 + c0);
        #pragma unroll
        for (int i = 0; i < 2; i++)
            #pragma unroll
            for (int j = 0; j < 4; j++) {
                float lo, hi;
                f2_unpack(lo, hi, f2_add(h[i][j], __double_as_longlong(b1d[j])));
                float g0 = 0.5f * lo * (1.f + erff(lo * 0.70710678118654752f));
                float g1 = 0.5f * hi * (1.f + erff(hi * 0.70710678118654752f));
                As[(2 * rg + i) * CTP + c0 + 2 * j]     = g0;
                As[(2 * rg + i) * CTP + c0 + 2 * j + 1] = g1;
            }
        __syncthreads();
        #pragma unroll 4
        for (int k = 0; k < 128; k++) {
            const double* Wd = (const double*)(W2m + (half * 128 + k) * 128 + c0);
            u64 w0 = __double_as_longlong(Wd[0]);
            u64 w1 = __double_as_longlong(Wd[1]);
            u64 w2 = __double_as_longlong(Wd[2]);
            u64 w3 = __double_as_longlong(Wd[3]);
            float s0 = As[(2 * rg) * CTP + k];
            float s1 = As[(2 * rg + 1) * CTP + k];
            u64 a0 = f2_pack(s0, s0);
            u64 a1 = f2_pack(s1, s1);
            acc2[0][0] = f2_fma(a0, w0, acc2[0][0]); acc2[0][1] = f2_fma(a0, w1, acc2[0][1]);
            acc2[0][2] = f2_fma(a0, w2, acc2[0][2]); acc2[0][3] = f2_fma(a0, w3, acc2[0][3]);
            acc2[1][0] = f2_fma(a1, w0, acc2[1][0]); acc2[1][1] = f2_fma(a1, w1, acc2[1][1]);
            acc2[1][2] = f2_fma(a1, w2, acc2[1][2]); acc2[1][3] = f2_fma(a1, w3, acc2[1][3]);
        }
        __syncthreads();
    }
    {
        const double* b2d = (const double*)(b2v + c0);
        #pragma unroll
        for (int i = 0; i < 2; i++) {
            u64* dst = (u64*)&Bs[(2 * rg + i) * CTP + c0];
            #pragma unroll
            for (int j = 0; j < 4; j++)
                dst[j] = f2_add(dst[j], f2_add(acc2[i][j], __double_as_longlong(b2d[j])));
        }
    }
    __syncthreads();
    // ---- post-LN ----
    if (tid < 32) {
        float s = 0.f, s2 = 0.f;
        const float* row = &Bs[tid * CTP];
        #pragma unroll 8
        for (int c = 0; c < 128; c++) { float x = row[c]; s += x; s2 += x * x; }
        float mn = s * (1.f / 128.f);
        float vv = s2 * (1.f / 128.f) - mn * mn;
        sm[tid] = mn; sr[tid] = rsqrtf(vv + 1e-5f);
    }
    __syncthreads();
    // ---- write transposed output (B, d, H, W) ----
    for (int idx = tid; idx < 4096; idx += 256) {
        int c = idx >> 5, r = idx & 31;
        float z = (Bs[r * CTP + c] - sm[r]) * sr[r] * postg[c] + postb[c];
        outp[((size_t)(b * DIMC + c)) * QCNT + q0 + r] = z;
    }
}

// ==================================================================
extern "C" void kernel_launch(void* const* d_in, const int* in_sizes, int n_in,
                              void* d_out, int out_size)
{
    const float* q     = (const float*)d_in[0];
    const float* k     = (const float*)d_in[1];
    const float* v     = (const float*)d_in[2];
    const float* skip  = (const float*)d_in[3];
    const float* lnq_g = (const float*)d_in[4];
    const float* lnq_b = (const float*)d_in[5];
    const float* Wq    = (const float*)d_in[6];
    const float* bq    = (const float*)d_in[7];
    const float* lnk_g = (const float*)d_in[8];
    const float* lnk_b = (const float*)d_in[9];
    const float* Wk    = (const float*)d_in[10];
    const float* bk    = (const float*)d_in[11];
    const float* lnv_g = (const float*)d_in[12];
    const float* lnv_b = (const float*)d_in[13];
    const float* Wv    = (const float*)d_in[14];
    const float* bv    = (const float*)d_in[15];
    const float* Wp    = (const float*)d_in[16];
    const float* bp    = (const float*)d_in[17];
    const float* pre_g = (const float*)d_in[18];
    const float* pre_b = (const float*)d_in[19];
    const float* W1    = (const float*)d_in[20];
    const float* b1    = (const float*)d_in[21];
    const float* W2    = (const float*)d_in[22];
    const float* b2    = (const float*)d_in[23];
    const float* post_g= (const float*)d_in[24];
    const float* post_b= (const float*)d_in[25];
    float* outp = (float*)d_out;

    float *qp, *kpb, *vpb, *Opart, *mlb;
    cudaGetSymbolAddress((void**)&qp,   g_qp);
    cudaGetSymbolAddress((void**)&kpb,  g_kp);
    cudaGetSymbolAddress((void**)&vpb,  g_vp);
    cudaGetSymbolAddress((void**)&Opart,g_Opart);
    cudaGetSymbolAddress((void**)&mlb,  g_ml);

    proj_all_kernel<<<648, 256>>>(q, k, v,
        lnq_g, lnq_b, Wq, bq, lnk_g, lnk_b, Wk, bk, lnv_g, lnv_b, Wv, bv,
        qp, kpb, vpb);

    dim3 ag(QCNT / 128, NV, BH);
    attn_kernel<<<ag, 64>>>(qp, kpb, vpb, Opart, mlb);

    tail_kernel<<<(BB * QCNT) / 32, 256>>>(Opart, mlb, skip, Wp, bp, pre_g, pre_b,
                                           W1, b1, W2, b2, post_g, post_b, outp);
}